// round 17
// baseline (speedup 1.0000x reference)
#include <cuda_runtime.h>

#define NCAM 6
#define C    64
#define HF   64
#define WF   176
#define NY   4
#define ZD   129
#define XD   129
#define NH   3
#define DD   128
#define WDIM 128
#define NVOX (NH * DD * WDIM)   // 49152
#define SPITCH 180              // padded smem row stride (720B, 16B-aligned)

// Scratch (static device globals: allocation-free per harness rules)
__device__ float  g_integ[NCAM * HF * WF * C];   // [n][h][w][c]
__device__ float2 g_nc[NCAM * NY * ZD * XD];     // projected corners

// ---------------------------------------------------------------------------
// Kernel 1: row-wise inclusive scan, written DIRECTLY channels-last.
// Block = (n, h, channel-block of 8). Lane loads one float4 (44 per row),
// local 3-add scan + one warp-shuffle scan over totals -> 2.6x shorter
// dependency chain than 6-segment scalar scan. Then transposed STG.128 write.
// ---------------------------------------------------------------------------
__global__ void __launch_bounds__(256) rowscan_t_kernel(const float* __restrict__ feat) {
    __shared__ float tile[8 * SPITCH];
    const int bid = blockIdx.x;
    const int cb  = bid & 7;                 // channel block (8 channels)
    const int h   = (bid >> 3) & (HF - 1);
    const int n   = bid >> 9;                // bid / (HF*8)
    const int lane = threadIdx.x & 31;
    const int wp   = threadIdx.x >> 5;       // warp -> local channel
    const int c    = cb * 8 + wp;

    const float4* src4 = (const float4*)(feat + (((size_t)(n * C + c) * HF) + h) * WF);
    float4* trow4 = (float4*)(tile + wp * SPITCH);

    float carry = 0.f;
    #pragma unroll
    for (int seg = 0; seg < 2; seg++) {
        const int i4 = seg * 32 + lane;      // float4 index; 44 total
        float4 v = (i4 < 44) ? __ldg(src4 + i4) : make_float4(0.f, 0.f, 0.f, 0.f);
        // local inclusive scan of 4
        v.y += v.x; v.z += v.y; v.w += v.z;
        const float tot = v.w;
        // warp inclusive scan of totals
        float inc = tot;
        #pragma unroll
        for (int off = 1; off < 32; off <<= 1) {
            float u = __shfl_up_sync(0xffffffffu, inc, off);
            if (lane >= off) inc += u;
        }
        const float pre = (inc - tot) + carry;   // exclusive prefix + carry
        v.x += pre; v.y += pre; v.z += pre; v.w += pre;
        if (i4 < 44) trow4[i4] = v;
        carry += __shfl_sync(0xffffffffu, inc, 31);
    }
    __syncthreads();

    // Transposed write: task = (w, channel-group of 4) -> STG.128.
    float4* dst4 = (float4*)(g_integ + (((size_t)n * HF + h) * WF) * C + cb * 8);
    #pragma unroll
    for (int iter = 0; iter < 2; iter++) {
        const int idx = threadIdx.x + iter * 256;
        if (idx < 2 * WF) {
            const int grp = idx & 1;
            const int w   = idx >> 1;
            const float* trow = tile + (grp * 4) * SPITCH + w;
            float4 v;
            v.x = trow[0];
            v.y = trow[SPITCH];
            v.z = trow[2 * SPITCH];
            v.w = trow[3 * SPITCH];
            dst4[(size_t)w * (C / 4) + grp] = v;
        }
    }
}

// ---------------------------------------------------------------------------
// Kernel 2 (fused): blocks [0, 264) column-scan g_integ in place over h;
// blocks [264, ...) project grid corners.
// ---------------------------------------------------------------------------
#define NCOLB (NCAM * WF * C / 256)   // 264 column-scan blocks (exact)
__global__ void __launch_bounds__(256) colproj_kernel(
        const float* __restrict__ ks,
        const float* __restrict__ m2c,
        const float* __restrict__ prot,
        const float* __restrict__ ptran,
        const float* __restrict__ und,
        const float* __restrict__ grid) {
    const int bid = blockIdx.x;

    if (bid < NCOLB) {
        const int idx = bid * 256 + threadIdx.x;     // = (n*WF + w)*C + c
        const int n   = idx / (WF * C);
        const int rem = idx - n * (WF * C);          // w*C + c
        float* p = g_integ + (size_t)n * HF * WF * C + rem;
        const int stride = WF * C;

        float acc = 0.f;
        #pragma unroll 1
        for (int h = 0; h < HF; h += 8) {
            float v0 = p[0];
            float v1 = p[stride];
            float v2 = p[2 * stride];
            float v3 = p[3 * stride];
            float v4 = p[4 * stride];
            float v5 = p[5 * stride];
            float v6 = p[6 * stride];
            float v7 = p[7 * stride];
            acc += v0; p[0]          = acc;
            acc += v1; p[stride]     = acc;
            acc += v2; p[2 * stride] = acc;
            acc += v3; p[3 * stride] = acc;
            acc += v4; p[4 * stride] = acc;
            acc += v5; p[5 * stride] = acc;
            acc += v6; p[6 * stride] = acc;
            acc += v7; p[7 * stride] = acc;
            p += 8 * stride;
        }
        return;
    }

    // ---- projection ----
    const int id = (bid - NCOLB) * 256 + threadIdx.x;
    const int total = NCAM * NY * ZD * XD;
    if (id >= total) return;
    const int xi = id % XD;
    const int zi = (id / XD) % ZD;
    const int ny = (id / (XD * ZD)) % NY;
    const int n  = id / (XD * ZD * NY);

    const float* K  = ks    + n * 9;
    const float* M  = m2c   + n * 12;
    const float* PR = prot  + n * 9;
    const float* PT = ptran + n * 3;
    const float* Dd = und   + n * 7;

    float cal[3][4];
    #pragma unroll
    for (int i = 0; i < 3; i++)
        #pragma unroll
        for (int j = 0; j < 4; j++)
            cal[i][j] = K[i*3+0]*M[0*4+j] + K[i*3+1]*M[1*4+j] + K[i*3+2]*M[2*4+j];

    const float* g = grid + ((size_t)zi * XD + xi) * 3;
    const float vx = g[0];
    const float vy = g[1] + (2.0f - (float)ny);
    const float vz = g[2];

    float hx = cal[0][0]*vx + cal[0][1]*vy + cal[0][2]*vz + cal[0][3];
    float hy = cal[1][0]*vx + cal[1][1]*vy + cal[1][2]*vz + cal[1][3];
    float hz = cal[2][0]*vx + cal[2][1]*vy + cal[2][2]*vz + cal[2][3];

    const float posf = (hz > 0.f) ? 1.f : 0.f;
    hx *= posf; hy *= posf;
    const float px = hx / hz, py = hy / hz;

    const float cx = K[2], cy = K[5], fx = K[0], fy = K[4];
    const float x = (px - cx) / fx, y = (py - cy) / fy;

    float xd, yd;
    if (Dd[6] == 1.0f) {
        float r  = sqrtf(x*x + y*y);
        float th = atanf(r);
        float t2 = th * th;
        float t4 = t2 * t2;
        float rad = th * (1.f + Dd[0]*t2 + Dd[1]*t4 + Dd[2]*t4*t2 + Dd[5]*t4*t4) / r;
        xd = x * rad * fx + cx;
        yd = y * rad * fy + cy;
    } else {
        float r2 = x*x + y*y;
        float r4 = r2 * r2;
        float poly = 1.f + Dd[0]*r2 + Dd[1]*r4 + Dd[2]*r4*r2;
        float p1 = Dd[3], p2 = Dd[4];
        float xdd = x*poly + (2.f*p1*x*y + p2*(r2 + 2.f*x*x));
        float ydd = y*poly + (p1*(r2 + 2.f*y*y) + 2.f*p2*x*y);
        xd = xdd * fx + cx;
        yd = ydd * fy + cy;
    }
    xd *= posf; yd *= posf;

    const float qx = PR[0]*xd + PR[1]*yd + PT[0];
    const float qy = PR[3]*xd + PR[4]*yd + PT[1];

    float2 o;
    o.x = fminf(fmaxf(2.f*qx - 1.f, -1.f), 1.f);
    o.y = fminf(fmaxf(2.f*qy - 1.f, -1.f), 1.f);
    g_nc[id] = o;
}

// ---------------------------------------------------------------------------
// Kernel 3 (proven form): 2 voxels per warp via LDG.128. Block 32x8 covers
// 16 voxels. Inactive tasks get zeroed descriptors; warp skips a cam only
// when BOTH voxels are inactive.
// ---------------------------------------------------------------------------
__global__ void __launch_bounds__(256) vox_kernel(float* __restrict__ out) {
    const int nhd = blockIdx.x >> 3;             // 8 blocks per (nh,d) row
    const int d   = nhd & 127;
    const int nh  = nhd >> 7;
    const int wd0 = (blockIdx.x & 7) << 4;       // 16 voxels per block
    const int tid = threadIdx.y * 32 + threadIdx.x;

    __shared__ int   s_off[96 * 16];    // texel offsets (float4 units)
    __shared__ float s_c[96 * 16];      // combined coefficients
    __shared__ int   s_act[96];         // active flag per (cam,voxel)
    __shared__ float res[C * 17];       // output staging [ch][vloc] pitch 17

    // ---- Geometry phase: one task per thread, task = cam*16 + vloc ----
    if (tid < 96) {
        const int cam = tid >> 4, vloc = tid & 15;
        const int wd = wd0 + vloc;
        const float2* ncp = g_nc + cam * (NY * ZD * XD) + ((size_t)nh * ZD + d) * XD + wd;

        float l = 1e30f, r = -1e30f, tp = 1e30f, bt = -1e30f;
        #pragma unroll
        for (int a = 0; a < 2; a++)
            #pragma unroll
            for (int b = 0; b < 2; b++)
                #pragma unroll
                for (int cc2 = 0; cc2 < 2; cc2++) {
                    float2 p = __ldg(ncp + (a * ZD + b) * XD + cc2);
                    l  = fminf(l,  p.x); r  = fmaxf(r,  p.x);
                    tp = fminf(tp, p.y); bt = fmaxf(bt, p.y);
                }

        const float area = (r - l) * (bt - tp) * (HF * WF * 0.25f) + 1e-6f;
        const int ok = (area > 1e-6f) ? 1 : 0;
        s_act[tid] = ok;
        if (ok) {
            float pxl = fminf(fmaxf((l  + 1.f) * 87.5f, 0.f), 175.f);
            float pxr = fminf(fmaxf((r  + 1.f) * 87.5f, 0.f), 175.f);
            float pyt = fminf(fmaxf((tp + 1.f) * 31.5f, 0.f), 63.f);
            float pyb = fminf(fmaxf((bt + 1.f) * 31.5f, 0.f), 63.f);

            float fxl = floorf(pxl), fxr = floorf(pxr);
            float fyt = floorf(pyt), fyb = floorf(pyb);
            float wxl = pxl - fxl, wxr = pxr - fxr;
            float wyt = pyt - fyt, wyb = pyb - fyb;

            int xs[4], ys[4];
            xs[0] = (int)fxl; xs[1] = min(xs[0] + 1, WF - 1);
            xs[2] = (int)fxr; xs[3] = min(xs[2] + 1, WF - 1);
            ys[0] = (int)fyt; ys[1] = min(ys[0] + 1, HF - 1);
            ys[2] = (int)fyb; ys[3] = min(ys[2] + 1, HF - 1);

            const float inv = 1.0f / area;
            float cxv[4] = {1.f - wxl, wxl, -(1.f - wxr), -wxr};
            float cyv[4] = {(1.f - wyt) * inv, wyt * inv,
                            -(1.f - wyb) * inv, -wyb * inv};

            #pragma unroll
            for (int i = 0; i < 4; i++) {
                const int yb = ys[i] * WF;
                #pragma unroll
                for (int j = 0; j < 4; j++) {
                    s_off[tid * 16 + i * 4 + j] = (yb + xs[j]) * (C / 4);
                    s_c[tid * 16 + i * 4 + j]   = cyv[i] * cxv[j];
                }
            }
        } else {
            #pragma unroll
            for (int k = 0; k < 16; k++) {
                s_off[tid * 16 + k] = 0;
                s_c[tid * 16 + k]   = 0.f;
            }
        }
    }
    __syncthreads();

    // ---- Gather phase ----
    const int q    = threadIdx.x & 15;           // channel quad (4 channels)
    const int half = threadIdx.x >> 4;           // voxel within pair
    float4 m = make_float4(-3.402823466e38f, -3.402823466e38f,
                           -3.402823466e38f, -3.402823466e38f);

    #pragma unroll 1
    for (int n = 0; n < NCAM; n++) {
        const int tA = n * 16 + 2 * threadIdx.y;
        if ((s_act[tA] | s_act[tA + 1]) == 0) {
            m.x = fmaxf(m.x, 0.f); m.y = fmaxf(m.y, 0.f);
            m.z = fmaxf(m.z, 0.f); m.w = fmaxf(m.w, 0.f);
            continue;
        }
        const int task = tA + half;
        const int4*   so = (const int4*)  (s_off + task * 16);
        const float4* sc = (const float4*)(s_c   + task * 16);
        const float4* base = (const float4*)(g_integ + (size_t)n * HF * WF * C) + q;

        float4 acc = make_float4(0.f, 0.f, 0.f, 0.f);
        #pragma unroll
        for (int g = 0; g < 4; g++) {
            const int4   o  = so[g];
            const float4 cc = sc[g];
            float4 a = __ldg(base + o.x), b = __ldg(base + o.y);
            float4 c = __ldg(base + o.z), e = __ldg(base + o.w);
            acc.x = fmaf(a.x, cc.x, fmaf(b.x, cc.y, fmaf(c.x, cc.z, fmaf(e.x, cc.w, acc.x))));
            acc.y = fmaf(a.y, cc.x, fmaf(b.y, cc.y, fmaf(c.y, cc.z, fmaf(e.y, cc.w, acc.y))));
            acc.z = fmaf(a.z, cc.x, fmaf(b.z, cc.y, fmaf(c.z, cc.z, fmaf(e.z, cc.w, acc.z))));
            acc.w = fmaf(a.w, cc.x, fmaf(b.w, cc.y, fmaf(c.w, cc.z, fmaf(e.w, cc.w, acc.w))));
        }
        m.x = fmaxf(m.x, acc.x); m.y = fmaxf(m.y, acc.y);
        m.z = fmaxf(m.z, acc.z); m.w = fmaxf(m.w, acc.w);
    }

    // ---- Output staging ----
    {
        const int vloc = 2 * threadIdx.y + half;
        res[(4 * q    ) * 17 + vloc] = m.x;
        res[(4 * q + 1) * 17 + vloc] = m.y;
        res[(4 * q + 2) * 17 + vloc] = m.z;
        res[(4 * q + 3) * 17 + vloc] = m.w;
    }
    __syncthreads();

    #pragma unroll
    for (int rep = 0; rep < 4; rep++) {
        const int idx = tid + rep * 256;         // 0..1023 = ch*16 + j
        const int ch  = idx >> 4;
        const int j   = idx & 15;
        out[((size_t)(ch * NH + nh) * DD + d) * WDIM + wd0 + j] = res[ch * 17 + j];
    }
}

// ---------------------------------------------------------------------------
extern "C" void kernel_launch(void* const* d_in, const int* in_sizes, int n_in,
                              void* d_out, int out_size) {
    (void)in_sizes; (void)n_in; (void)out_size;
    const float* features  = (const float*)d_in[0];
    const float* ks        = (const float*)d_in[1];
    const float* imu2cs    = (const float*)d_in[2];
    const float* post_rots = (const float*)d_in[3];
    const float* post_trans= (const float*)d_in[4];
    const float* undists   = (const float*)d_in[5];
    const float* grid      = (const float*)d_in[6];
    float* out = (float*)d_out;

    rowscan_t_kernel<<<NCAM * HF * (C / 8), 256>>>(features);

    const int totalP = NCAM * NY * ZD * XD;
    const int projBlocks = (totalP + 255) / 256;     // 1561
    colproj_kernel<<<NCOLB + projBlocks, 256>>>(ks, imu2cs, post_rots,
                                                post_trans, undists, grid);

    dim3 blk(32, 8);
    vox_kernel<<<(NH * DD * WDIM) / 16, blk>>>(out);
}